// round 5
// baseline (speedup 1.0000x reference)
#include <cuda_runtime.h>
#include <cstdint>
#include <math.h>

#define BATCH 2
#define SEQ   2048
#define DMODEL 2048
#define NH    16
#define HD    128
#define CACHEDLEN 2048

// ---------------- scratch (static device globals) ----------------
__device__ float g_Q [(size_t)BATCH*NH*SEQ*HD];   // [B,H,S,HD] pre-scaled+rounded
__device__ float g_Kn[(size_t)BATCH*NH*SEQ*HD];   // [B,H,S,HD] rounded
__device__ float g_Vn[(size_t)BATCH*NH*SEQ*HD];   // [B,H,S,HD] rounded
__device__ float g_At[(size_t)BATCH*SEQ*DMODEL];  // [B,S,D]    rounded
__device__ float g_X [(size_t)BATCH*SEQ*DMODEL];  // rounded hidden states
__device__ float g_Wr[(size_t)4*DMODEL*DMODEL];   // rounded Wq,Wk,Wv,Wo
__device__ float g_Kc[(size_t)BATCH*NH*CACHEDLEN*HD];  // rounded k_cache
__device__ float g_Vc[(size_t)BATCH*NH*CACHEDLEN*HD];  // rounded v_cache

// ================= helpers =================
__device__ __forceinline__ uint32_t smem_u32(const void* p) {
    uint32_t a;
    asm("{ .reg .u64 t; cvta.to.shared.u64 t, %1; cvt.u32.u64 %0, t; }" : "=r"(a) : "l"(p));
    return a;
}
__device__ __forceinline__ void cp_async16(uint32_t saddr, const void* gptr) {
    asm volatile("cp.async.cg.shared.global [%0], [%1], 16;\n" :: "r"(saddr), "l"(gptr));
}
#define CP_COMMIT() asm volatile("cp.async.commit_group;\n" ::: "memory")
#define CP_WAIT1()  asm volatile("cp.async.wait_group 1;\n" ::: "memory")

__device__ __forceinline__ uint32_t f2tf32(float f) {
    uint32_t r;
    asm("cvt.rna.tf32.f32 %0, %1;" : "=r"(r) : "f"(f));
    return r;
}
__device__ __forceinline__ float roundtf(float f) { return __uint_as_float(f2tf32(f)); }

__device__ __forceinline__ void mma_tf32(float c[4], const uint32_t a[4], const uint32_t b[2]) {
    asm volatile(
        "mma.sync.aligned.m16n8k8.row.col.f32.tf32.tf32.f32 "
        "{%0,%1,%2,%3}, {%4,%5,%6,%7}, {%8,%9}, {%0,%1,%2,%3};"
        : "+f"(c[0]), "+f"(c[1]), "+f"(c[2]), "+f"(c[3])
        : "r"(a[0]), "r"(a[1]), "r"(a[2]), "r"(a[3]), "r"(b[0]), "r"(b[1]));
}

// ================= tf32 pre-rounding kernel =================
__global__ __launch_bounds__(256) void round_tf32_k(const float4* __restrict__ in,
                                                    float4* __restrict__ out, int n4)
{
    for (int i = blockIdx.x * blockDim.x + threadIdx.x; i < n4;
         i += gridDim.x * blockDim.x) {
        float4 v = in[i];
        v.x = roundtf(v.x); v.y = roundtf(v.y);
        v.z = roundtf(v.z); v.w = roundtf(v.w);
        out[i] = v;
    }
}

// ================= tf32 mma.sync GEMM (inputs pre-rounded, no inner cvt) =====
// MODE 0: plain row-major out (final, unrounded).
// MODE 1: scatter to [B,H,S,HD], rounded.
// MODE 2: scatter to [B,H,S,HD], scaled by 1/sqrt(HD) then rounded (Q).
#define BK       32
#define NCHUNK   (DMODEL / BK)
#define ROWPAD   36
#define TILE_FLOATS (128 * ROWPAD)
#define STAGE_FLOATS (2 * TILE_FLOATS)
#define NSTAGES  3
#define GEMM_SMEM (NSTAGES * STAGE_FLOATS * 4)

__device__ __forceinline__ void load_stage(const float* __restrict__ A,
                                           const float* __restrict__ W,
                                           int m0, int n0, int k0,
                                           float* stage, int tid)
{
    uint32_t sa = smem_u32(stage);
#pragma unroll
    for (int i = 0; i < 4; ++i) {
        int c = tid + 256 * i;
        int row = c >> 3;
        int j = c & 7;
        cp_async16(sa + (uint32_t)(row * (ROWPAD * 4) + j * 16),
                   A + (size_t)(m0 + row) * DMODEL + k0 + j * 4);
    }
    uint32_t sb = sa + TILE_FLOATS * 4;
#pragma unroll
    for (int i = 0; i < 4; ++i) {
        int c = tid + 256 * i;
        int row = c >> 3;
        int j = c & 7;
        cp_async16(sb + (uint32_t)(row * (ROWPAD * 4) + j * 16),
                   W + (size_t)(n0 + row) * DMODEL + k0 + j * 4);
    }
}

template <int MODE>
__global__ __launch_bounds__(256) void gemm_mma(const float* __restrict__ A,
                                                const float* __restrict__ W,
                                                float* __restrict__ C)
{
    extern __shared__ float sm[];
    int tid = threadIdx.x;
    int lane = tid & 31;
    int w = tid >> 5;
    int wm = w >> 2;
    int wn = w & 3;
    int g  = lane >> 2;
    int tg = lane & 3;
    int m0 = blockIdx.y * 128, n0 = blockIdx.x * 128;

    float acc[4][4][4];
#pragma unroll
    for (int i = 0; i < 4; ++i)
#pragma unroll
        for (int j = 0; j < 4; ++j)
#pragma unroll
            for (int r = 0; r < 4; ++r) acc[i][j][r] = 0.f;

    load_stage(A, W, m0, n0, 0, sm, tid);
    CP_COMMIT();
    load_stage(A, W, m0, n0, BK, sm + STAGE_FLOATS, tid);
    CP_COMMIT();

    for (int it = 0; it < NCHUNK; ++it) {
        const float* As = sm + (it % NSTAGES) * STAGE_FLOATS;
        const float* Bs = As + TILE_FLOATS;
        CP_WAIT1();
        __syncthreads();

#pragma unroll
        for (int s = 0; s < 4; ++s) {
            int kc0 = 8 * s + tg;
            int kc1 = kc0 + 4;
            uint32_t af[4][4], bf[4][2];
#pragma unroll
            for (int mi = 0; mi < 4; ++mi) {
                int r0 = wm * 64 + mi * 16 + g;
                af[mi][0] = __float_as_uint(As[r0 * ROWPAD + kc0]);
                af[mi][1] = __float_as_uint(As[(r0 + 8) * ROWPAD + kc0]);
                af[mi][2] = __float_as_uint(As[r0 * ROWPAD + kc1]);
                af[mi][3] = __float_as_uint(As[(r0 + 8) * ROWPAD + kc1]);
            }
#pragma unroll
            for (int nj = 0; nj < 4; ++nj) {
                int c0 = wn * 32 + nj * 8 + g;
                bf[nj][0] = __float_as_uint(Bs[c0 * ROWPAD + kc0]);
                bf[nj][1] = __float_as_uint(Bs[c0 * ROWPAD + kc1]);
            }
#pragma unroll
            for (int mi = 0; mi < 4; ++mi)
#pragma unroll
                for (int nj = 0; nj < 4; ++nj)
                    mma_tf32(acc[mi][nj], af[mi], bf[nj]);
        }

        if (it + 2 < NCHUNK)
            load_stage(A, W, m0, n0, (it + 2) * BK,
                       sm + ((it + 2) % NSTAGES) * STAGE_FLOATS, tid);
        CP_COMMIT();
    }

    const float qscale = 0.088388347648318447f;
#pragma unroll
    for (int mi = 0; mi < 4; ++mi) {
#pragma unroll
        for (int nj = 0; nj < 4; ++nj) {
            int m = m0 + wm * 64 + mi * 16 + g;
            int n = n0 + wn * 32 + nj * 8 + 2 * tg;
            float v0 = acc[mi][nj][0], v1 = acc[mi][nj][1];
            float v2 = acc[mi][nj][2], v3 = acc[mi][nj][3];
            if (MODE == 2) { v0 *= qscale; v1 *= qscale; v2 *= qscale; v3 *= qscale; }
            if (MODE != 0) { v0 = roundtf(v0); v1 = roundtf(v1);
                             v2 = roundtf(v2); v3 = roundtf(v3); }
            float2 lo = make_float2(v0, v1);
            float2 hi = make_float2(v2, v3);
            if (MODE == 0) {
                *reinterpret_cast<float2*>(C + (size_t)m * DMODEL + n) = lo;
                *reinterpret_cast<float2*>(C + (size_t)(m + 8) * DMODEL + n) = hi;
            } else {
                int h_  = n >> 7;
                int hd_ = n & 127;
                {
                    int b_ = m >> 11, s_ = m & 2047;
                    *reinterpret_cast<float2*>(
                        C + ((((size_t)b_ * NH + h_) * SEQ + s_) * HD + hd_)) = lo;
                }
                {
                    int m2 = m + 8;
                    int b_ = m2 >> 11, s_ = m2 & 2047;
                    *reinterpret_cast<float2*>(
                        C + ((((size_t)b_ * NH + h_) * SEQ + s_) * HD + hd_)) = hi;
                }
            }
        }
    }
}

// ================= tensor-core flash attention (pre-rounded inputs) ==========
#define DPAD 132
#define PPAD 68
#define KV_STAGE (2 * 64 * DPAD)
#define AT_PS    (2 * KV_STAGE)
#define AT_LROW  (AT_PS + 64 * PPAD)
#define ATTN_SMEM ((AT_LROW + 64) * 4)

__device__ __forceinline__ void load_kv(const float* __restrict__ kcb,
                                        const float* __restrict__ vcb,
                                        const float* __restrict__ knb,
                                        const float* __restrict__ vnb,
                                        int t0, float* stage, int tid)
{
    uint32_t sk = smem_u32(stage);
    uint32_t sv = sk + 64 * DPAD * 4;
#pragma unroll
    for (int i = 0; i < 8; ++i) {
        int idx = tid + 256 * i;
        int row = idx >> 5;
        int j = idx & 31;
        int t = t0 + row;
        const float *ks, *vs;
        if (t < CACHEDLEN) { ks = kcb + (size_t)t * HD; vs = vcb + (size_t)t * HD; }
        else               { ks = knb + (size_t)(t - CACHEDLEN) * HD;
                             vs = vnb + (size_t)(t - CACHEDLEN) * HD; }
        cp_async16(sk + (uint32_t)(row * (DPAD * 4) + j * 16), ks + j * 4);
        cp_async16(sv + (uint32_t)(row * (DPAD * 4) + j * 16), vs + j * 4);
    }
}

__global__ __launch_bounds__(256) void attn_tc(
    const float* __restrict__ Q,
    const float* __restrict__ Kn,
    const float* __restrict__ Vn,
    const float* __restrict__ kc,
    const float* __restrict__ vc,
    float* __restrict__ O)
{
    extern __shared__ float sm[];
    float* Ps   = sm + AT_PS;
    float* lrow = sm + AT_LROW;

    int qt = blockIdx.x, h = blockIdx.y, b = blockIdx.z;
    int tid = threadIdx.x, lane = tid & 31, w = tid >> 5;
    int wm = w >> 1, wn = w & 1;
    int g = lane >> 2, tg = lane & 3;
    int q0 = qt * 64;
    size_t bh = (size_t)b * NH + h;

    if (tid < 64) lrow[tid] = 0.f;

    const float* kcb = kc + bh * CACHEDLEN * HD;
    const float* vcb = vc + bh * CACHEDLEN * HD;
    const float* knb = Kn + bh * SEQ * HD;
    const float* vnb = Vn + bh * SEQ * HD;

    // Q fragments in registers (already scaled+rounded in gmem)
    const float* Qg = Q + (bh * SEQ + q0) * HD;
    int r0 = wm * 16 + g;
    uint32_t qf[16][4];
#pragma unroll
    for (int s = 0; s < 16; ++s) {
        int k0 = 8 * s + tg;
        qf[s][0] = __float_as_uint(Qg[(size_t)r0 * HD + k0]);
        qf[s][1] = __float_as_uint(Qg[(size_t)(r0 + 8) * HD + k0]);
        qf[s][2] = __float_as_uint(Qg[(size_t)r0 * HD + k0 + 4]);
        qf[s][3] = __float_as_uint(Qg[(size_t)(r0 + 8) * HD + k0 + 4]);
    }

    float oa[8][4];
#pragma unroll
    for (int j = 0; j < 8; ++j)
#pragma unroll
        for (int r = 0; r < 4; ++r) oa[j][r] = 0.f;

    int nt = (CACHEDLEN + q0 + 64) / 64;
    load_kv(kcb, vcb, knb, vnb, 0, sm, tid);
    CP_COMMIT();

    for (int it = 0; it < nt; ++it) {
        if (it + 1 < nt)
            load_kv(kcb, vcb, knb, vnb, (it + 1) * 64, sm + ((it + 1) & 1) * KV_STAGE, tid);
        CP_COMMIT();
        CP_WAIT1();
        __syncthreads();

        const float* Ks = sm + (it & 1) * KV_STAGE;
        const float* Vs = Ks + 64 * DPAD;

        // ---- S = Q K^T : warp tile 16x32 ----
        float sc[4][4];
#pragma unroll
        for (int nj = 0; nj < 4; ++nj)
#pragma unroll
            for (int r = 0; r < 4; ++r) sc[nj][r] = 0.f;

#pragma unroll
        for (int s = 0; s < 16; ++s) {
            int kc0 = 8 * s + tg;
            uint32_t bf[4][2];
#pragma unroll
            for (int nj = 0; nj < 4; ++nj) {
                int t = wn * 32 + nj * 8 + g;
                bf[nj][0] = __float_as_uint(Ks[t * DPAD + kc0]);
                bf[nj][1] = __float_as_uint(Ks[t * DPAD + kc0 + 4]);
            }
#pragma unroll
            for (int nj = 0; nj < 4; ++nj)
                mma_tf32(sc[nj], qf[s], bf[nj]);
        }

        // ---- exp + mask + row sums + store P (rounded to tf32) ----
        int qa0 = CACHEDLEN + q0 + wm * 16 + g;
        int tb  = it * 64 + wn * 32;
        float rs0 = 0.f, rs1 = 0.f;
#pragma unroll
        for (int nj = 0; nj < 4; ++nj) {
            int c0 = tb + nj * 8 + 2 * tg;
            float p00 = (c0     <= qa0    ) ? roundtf(__expf(sc[nj][0])) : 0.f;
            float p01 = (c0 + 1 <= qa0    ) ? roundtf(__expf(sc[nj][1])) : 0.f;
            float p10 = (c0     <= qa0 + 8) ? roundtf(__expf(sc[nj][2])) : 0.f;
            float p11 = (c0 + 1 <= qa0 + 8) ? roundtf(__expf(sc[nj][3])) : 0.f;
            rs0 += p00 + p01;
            rs1 += p10 + p11;
            int pr = wm * 16 + g;
            int pcol = wn * 32 + nj * 8 + 2 * tg;
            *reinterpret_cast<float2*>(&Ps[pr * PPAD + pcol])       = make_float2(p00, p01);
            *reinterpret_cast<float2*>(&Ps[(pr + 8) * PPAD + pcol]) = make_float2(p10, p11);
        }
        rs0 += __shfl_xor_sync(0xffffffffu, rs0, 1);
        rs0 += __shfl_xor_sync(0xffffffffu, rs0, 2);
        rs1 += __shfl_xor_sync(0xffffffffu, rs1, 1);
        rs1 += __shfl_xor_sync(0xffffffffu, rs1, 2);
        if (tg == 0) {
            atomicAdd(&lrow[wm * 16 + g], rs0);
            atomicAdd(&lrow[wm * 16 + g + 8], rs1);
        }
        __syncthreads();

        // ---- O += P V : warp tile 16x64 ----
#pragma unroll
        for (int s = 0; s < 8; ++s) {
            uint32_t af[4];
            int kk = 8 * s + tg;
            af[0] = __float_as_uint(Ps[(wm * 16 + g) * PPAD + kk]);
            af[1] = __float_as_uint(Ps[(wm * 16 + g + 8) * PPAD + kk]);
            af[2] = __float_as_uint(Ps[(wm * 16 + g) * PPAD + kk + 4]);
            af[3] = __float_as_uint(Ps[(wm * 16 + g + 8) * PPAD + kk + 4]);
#pragma unroll
            for (int nj = 0; nj < 8; ++nj) {
                int d0 = wn * 64 + nj * 8 + g;
                uint32_t bf[2];
                bf[0] = __float_as_uint(Vs[(8 * s + tg) * DPAD + d0]);
                bf[1] = __float_as_uint(Vs[(8 * s + tg + 4) * DPAD + d0]);
                mma_tf32(oa[nj], af, bf);
            }
        }
        __syncthreads();
    }

    float inv0 = 1.f / lrow[wm * 16 + g];
    float inv1 = 1.f / lrow[wm * 16 + g + 8];
    int row0 = q0 + wm * 16 + g;
#pragma unroll
    for (int nj = 0; nj < 8; ++nj) {
        int d = wn * 64 + nj * 8 + 2 * tg;
        float* dst0 = O + ((size_t)b * SEQ + row0) * DMODEL + h * HD + d;
        float* dst1 = O + ((size_t)b * SEQ + row0 + 8) * DMODEL + h * HD + d;
        *reinterpret_cast<float2*>(dst0) =
            make_float2(roundtf(oa[nj][0] * inv0), roundtf(oa[nj][1] * inv0));
        *reinterpret_cast<float2*>(dst1) =
            make_float2(roundtf(oa[nj][2] * inv1), roundtf(oa[nj][3] * inv1));
    }
}

// ---------------- launch ----------------
extern "C" void kernel_launch(void* const* d_in, const int* in_sizes, int n_in,
                              void* d_out, int out_size)
{
    const float* X  = (const float*)d_in[0];
    const float* Wq = (const float*)d_in[1];
    const float* Wk = (const float*)d_in[2];
    const float* Wv = (const float*)d_in[3];
    const float* Wo = (const float*)d_in[4];
    const float* kc = (const float*)d_in[5];
    const float* vc = (const float*)d_in[6];

    float *Qp, *Kp, *Vp, *Ap, *Xp, *Wp, *Kcp, *Vcp;
    cudaGetSymbolAddress((void**)&Qp,  g_Q);
    cudaGetSymbolAddress((void**)&Kp,  g_Kn);
    cudaGetSymbolAddress((void**)&Vp,  g_Vn);
    cudaGetSymbolAddress((void**)&Ap,  g_At);
    cudaGetSymbolAddress((void**)&Xp,  g_X);
    cudaGetSymbolAddress((void**)&Wp,  g_Wr);
    cudaGetSymbolAddress((void**)&Kcp, g_Kc);
    cudaGetSymbolAddress((void**)&Vcp, g_Vc);

    cudaFuncSetAttribute(gemm_mma<0>, cudaFuncAttributeMaxDynamicSharedMemorySize, GEMM_SMEM);
    cudaFuncSetAttribute(gemm_mma<1>, cudaFuncAttributeMaxDynamicSharedMemorySize, GEMM_SMEM);
    cudaFuncSetAttribute(gemm_mma<2>, cudaFuncAttributeMaxDynamicSharedMemorySize, GEMM_SMEM);
    cudaFuncSetAttribute(attn_tc, cudaFuncAttributeMaxDynamicSharedMemorySize, ATTN_SMEM);

    const int NX = BATCH * SEQ * DMODEL / 4;      // float4 counts
    const int NW = DMODEL * DMODEL / 4;
    const int NC = BATCH * NH * CACHEDLEN * HD / 4;

    round_tf32_k<<<1024, 256>>>((const float4*)X,  (float4*)Xp,  NX);
    round_tf32_k<<<1024, 256>>>((const float4*)Wq, (float4*)(Wp + 0L * DMODEL * DMODEL), NW);
    round_tf32_k<<<1024, 256>>>((const float4*)Wk, (float4*)(Wp + 1L * DMODEL * DMODEL), NW);
    round_tf32_k<<<1024, 256>>>((const float4*)Wv, (float4*)(Wp + 2L * DMODEL * DMODEL), NW);
    round_tf32_k<<<1024, 256>>>((const float4*)Wo, (float4*)(Wp + 3L * DMODEL * DMODEL), NW);
    round_tf32_k<<<1024, 256>>>((const float4*)kc, (float4*)Kcp, NC);
    round_tf32_k<<<1024, 256>>>((const float4*)vc, (float4*)Vcp, NC);

    dim3 gg(DMODEL / 128, (BATCH * SEQ) / 128);

    gemm_mma<2><<<gg, 256, GEMM_SMEM>>>(Xp, Wp + 0L * DMODEL * DMODEL, Qp);
    gemm_mma<1><<<gg, 256, GEMM_SMEM>>>(Xp, Wp + 1L * DMODEL * DMODEL, Kp);
    gemm_mma<1><<<gg, 256, GEMM_SMEM>>>(Xp, Wp + 2L * DMODEL * DMODEL, Vp);

    attn_tc<<<dim3(SEQ / 64, NH, BATCH), 256, ATTN_SMEM>>>(Qp, Kp, Vp, Kcp, Vcp, Ap);

    gemm_mma<0><<<gg, 256, GEMM_SMEM>>>(Ap, Wp + 3L * DMODEL * DMODEL, (float*)d_out);
}

// round 6
// speedup vs baseline: 1.1621x; 1.1621x over previous
#include <cuda_runtime.h>
#include <cstdint>
#include <math.h>

#define BATCH 2
#define SEQ   2048
#define DMODEL 2048
#define NH    16
#define HD    128
#define CACHEDLEN 2048

// ---------------- scratch (static device globals) ----------------
__device__ float g_Q [(size_t)BATCH*NH*SEQ*HD];   // [B,H,S,HD] pre-scaled+rounded
__device__ float g_Kn[(size_t)BATCH*NH*SEQ*HD];   // [B,H,S,HD] rounded
__device__ float g_Vn[(size_t)BATCH*NH*SEQ*HD];   // [B,H,S,HD] rounded
__device__ float g_At[(size_t)BATCH*SEQ*DMODEL];  // [B,S,D]    rounded
__device__ float g_X [(size_t)BATCH*SEQ*DMODEL];  // rounded hidden states
__device__ float g_Wr[(size_t)4*DMODEL*DMODEL];   // rounded Wq,Wk,Wv,Wo
__device__ float g_Kc[(size_t)BATCH*NH*CACHEDLEN*HD];  // rounded k_cache
__device__ float g_Vc[(size_t)BATCH*NH*CACHEDLEN*HD];  // rounded v_cache

// ================= helpers =================
__device__ __forceinline__ uint32_t smem_u32(const void* p) {
    uint32_t a;
    asm("{ .reg .u64 t; cvta.to.shared.u64 t, %1; cvt.u32.u64 %0, t; }" : "=r"(a) : "l"(p));
    return a;
}
__device__ __forceinline__ void cp_async16(uint32_t saddr, const void* gptr) {
    asm volatile("cp.async.cg.shared.global [%0], [%1], 16;\n" :: "r"(saddr), "l"(gptr));
}
#define CP_COMMIT() asm volatile("cp.async.commit_group;\n" ::: "memory")
#define CP_WAIT1()  asm volatile("cp.async.wait_group 1;\n" ::: "memory")

__device__ __forceinline__ uint32_t f2tf32(float f) {
    uint32_t r;
    asm("cvt.rna.tf32.f32 %0, %1;" : "=r"(r) : "f"(f));
    return r;
}
__device__ __forceinline__ float roundtf(float f) { return __uint_as_float(f2tf32(f)); }

__device__ __forceinline__ void mma_tf32(float c[4], const uint32_t a[4], const uint32_t b[2]) {
    asm volatile(
        "mma.sync.aligned.m16n8k8.row.col.f32.tf32.tf32.f32 "
        "{%0,%1,%2,%3}, {%4,%5,%6,%7}, {%8,%9}, {%0,%1,%2,%3};"
        : "+f"(c[0]), "+f"(c[1]), "+f"(c[2]), "+f"(c[3])
        : "r"(a[0]), "r"(a[1]), "r"(a[2]), "r"(a[3]), "r"(b[0]), "r"(b[1]));
}
// ldmatrix: 4x (8 rows x 16B). For fp32 data each m8n8.b16 tile is an 8x4 fp32
// tile; thread l receives element (l/4, l%4) -- exactly the tf32 frag layout.
__device__ __forceinline__ void ldsm_x4(uint32_t r[4], uint32_t saddr) {
    asm volatile("ldmatrix.sync.aligned.m8n8.x4.shared.b16 {%0,%1,%2,%3}, [%4];"
                 : "=r"(r[0]), "=r"(r[1]), "=r"(r[2]), "=r"(r[3]) : "r"(saddr));
}

// ================= tf32 pre-rounding kernel (4-wide, MLP=4) =================
__global__ __launch_bounds__(256) void round_tf32_k(const float4* __restrict__ in,
                                                    float4* __restrict__ out, int n4)
{
    int i = (blockIdx.x * blockDim.x + threadIdx.x) * 4;
    if (i + 3 < n4) {
        float4 a = in[i], b = in[i+1], c = in[i+2], d = in[i+3];
        a.x=roundtf(a.x); a.y=roundtf(a.y); a.z=roundtf(a.z); a.w=roundtf(a.w);
        b.x=roundtf(b.x); b.y=roundtf(b.y); b.z=roundtf(b.z); b.w=roundtf(b.w);
        c.x=roundtf(c.x); c.y=roundtf(c.y); c.z=roundtf(c.z); c.w=roundtf(c.w);
        d.x=roundtf(d.x); d.y=roundtf(d.y); d.z=roundtf(d.z); d.w=roundtf(d.w);
        out[i] = a; out[i+1] = b; out[i+2] = c; out[i+3] = d;
    }
}

// ================= tf32 mma.sync GEMM (ldmatrix fragment loads) =====
#define BK       32
#define NCHUNK   (DMODEL / BK)
#define ROWPAD   36
#define TILE_FLOATS (128 * ROWPAD)
#define STAGE_FLOATS (2 * TILE_FLOATS)
#define NSTAGES  3
#define GEMM_SMEM (NSTAGES * STAGE_FLOATS * 4)

__device__ __forceinline__ void load_stage(const float* __restrict__ A,
                                           const float* __restrict__ W,
                                           int m0, int n0, int k0,
                                           uint32_t sa, int tid)
{
#pragma unroll
    for (int i = 0; i < 4; ++i) {
        int c = tid + 256 * i;
        int row = c >> 3;
        int j = c & 7;
        cp_async16(sa + (uint32_t)(row * (ROWPAD * 4) + j * 16),
                   A + (size_t)(m0 + row) * DMODEL + k0 + j * 4);
    }
    uint32_t sb = sa + TILE_FLOATS * 4;
#pragma unroll
    for (int i = 0; i < 4; ++i) {
        int c = tid + 256 * i;
        int row = c >> 3;
        int j = c & 7;
        cp_async16(sb + (uint32_t)(row * (ROWPAD * 4) + j * 16),
                   W + (size_t)(n0 + row) * DMODEL + k0 + j * 4);
    }
}

template <int MODE>
__global__ __launch_bounds__(256) void gemm_mma(const float* __restrict__ A,
                                                const float* __restrict__ W,
                                                float* __restrict__ C)
{
    extern __shared__ float sm[];
    uint32_t smb = smem_u32(sm);
    int tid = threadIdx.x;
    int lane = tid & 31;
    int w = tid >> 5;
    int wm = w >> 2;
    int wn = w & 3;
    int g  = lane >> 2;
    int tg = lane & 3;
    int m0 = blockIdx.y * 128, n0 = blockIdx.x * 128;

    // ldmatrix per-lane offsets (bytes, within tile)
    int lr16 = lane & 15;                                // A rows 0..15
    int lc4  = ((lane >> 4) & 1) * 4;                    // A col half
    int br   = (lane & 7) + ((lane >> 4) & 1) * 8;       // B rows
    int bc4  = ((lane >> 3) & 1) * 4;                    // B col half
    uint32_t a_off[4], b_off[2];
#pragma unroll
    for (int mi = 0; mi < 4; ++mi)
        a_off[mi] = (uint32_t)(((wm * 64 + mi * 16 + lr16) * ROWPAD + lc4) * 4);
#pragma unroll
    for (int njp = 0; njp < 2; ++njp)
        b_off[njp] = (uint32_t)(((wn * 32 + njp * 16 + br) * ROWPAD + bc4) * 4);

    float acc[4][4][4];
#pragma unroll
    for (int i = 0; i < 4; ++i)
#pragma unroll
        for (int j = 0; j < 4; ++j)
#pragma unroll
            for (int r = 0; r < 4; ++r) acc[i][j][r] = 0.f;

    load_stage(A, W, m0, n0, 0, smb, tid);
    CP_COMMIT();
    load_stage(A, W, m0, n0, BK, smb + STAGE_FLOATS * 4, tid);
    CP_COMMIT();

    for (int it = 0; it < NCHUNK; ++it) {
        uint32_t sA = smb + (uint32_t)((it % NSTAGES) * STAGE_FLOATS * 4);
        uint32_t sB = sA + TILE_FLOATS * 4;
        CP_WAIT1();
        __syncthreads();

#pragma unroll
        for (int s = 0; s < 4; ++s) {
            uint32_t koff = (uint32_t)(s * 32);
            uint32_t af[4][4], bq[2][4];
#pragma unroll
            for (int mi = 0; mi < 4; ++mi) ldsm_x4(af[mi], sA + a_off[mi] + koff);
#pragma unroll
            for (int njp = 0; njp < 2; ++njp) ldsm_x4(bq[njp], sB + b_off[njp] + koff);
#pragma unroll
            for (int mi = 0; mi < 4; ++mi)
#pragma unroll
                for (int nj = 0; nj < 4; ++nj)
                    mma_tf32(acc[mi][nj], af[mi], &bq[nj >> 1][(nj & 1) * 2]);
        }

        if (it + 2 < NCHUNK)
            load_stage(A, W, m0, n0, (it + 2) * BK,
                       smb + (uint32_t)(((it + 2) % NSTAGES) * STAGE_FLOATS * 4), tid);
        CP_COMMIT();
    }

    const float qscale = 0.088388347648318447f;
#pragma unroll
    for (int mi = 0; mi < 4; ++mi) {
#pragma unroll
        for (int nj = 0; nj < 4; ++nj) {
            int m = m0 + wm * 64 + mi * 16 + g;
            int n = n0 + wn * 32 + nj * 8 + 2 * tg;
            float v0 = acc[mi][nj][0], v1 = acc[mi][nj][1];
            float v2 = acc[mi][nj][2], v3 = acc[mi][nj][3];
            if (MODE == 2) { v0 *= qscale; v1 *= qscale; v2 *= qscale; v3 *= qscale; }
            if (MODE != 0) { v0 = roundtf(v0); v1 = roundtf(v1);
                             v2 = roundtf(v2); v3 = roundtf(v3); }
            float2 lo = make_float2(v0, v1);
            float2 hi = make_float2(v2, v3);
            if (MODE == 0) {
                *reinterpret_cast<float2*>(C + (size_t)m * DMODEL + n) = lo;
                *reinterpret_cast<float2*>(C + (size_t)(m + 8) * DMODEL + n) = hi;
            } else {
                int h_  = n >> 7;
                int hd_ = n & 127;
                {
                    int b_ = m >> 11, s_ = m & 2047;
                    *reinterpret_cast<float2*>(
                        C + ((((size_t)b_ * NH + h_) * SEQ + s_) * HD + hd_)) = lo;
                }
                {
                    int m2 = m + 8;
                    int b_ = m2 >> 11, s_ = m2 & 2047;
                    *reinterpret_cast<float2*>(
                        C + ((((size_t)b_ * NH + h_) * SEQ + s_) * HD + hd_)) = hi;
                }
            }
        }
    }
}

// ================= tensor-core flash attention =================
// K pad 132 (=4 mod 32: frag rows keyed by g); V pad 136 (=8 mod 32: rows keyed
// by tg) -- both conflict-free.
#define DPADK 132
#define VPADV 136
#define PPAD  68
#define KV_STAGE (64 * DPADK + 64 * VPADV)     // floats
#define AT_PS    (2 * KV_STAGE)
#define AT_LROW  (AT_PS + 64 * PPAD)
#define ATTN_SMEM ((AT_LROW + 64) * 4)

__device__ __forceinline__ void load_kv(const float* __restrict__ kcb,
                                        const float* __restrict__ vcb,
                                        const float* __restrict__ knb,
                                        const float* __restrict__ vnb,
                                        int t0, uint32_t sk, int tid)
{
    uint32_t sv = sk + 64 * DPADK * 4;
#pragma unroll
    for (int i = 0; i < 8; ++i) {
        int idx = tid + 256 * i;
        int row = idx >> 5;
        int j = idx & 31;
        int t = t0 + row;
        const float *ks, *vs;
        if (t < CACHEDLEN) { ks = kcb + (size_t)t * HD; vs = vcb + (size_t)t * HD; }
        else               { ks = knb + (size_t)(t - CACHEDLEN) * HD;
                             vs = vnb + (size_t)(t - CACHEDLEN) * HD; }
        cp_async16(sk + (uint32_t)(row * (DPADK * 4) + j * 16), ks + j * 4);
        cp_async16(sv + (uint32_t)(row * (VPADV * 4) + j * 16), vs + j * 4);
    }
}

__global__ __launch_bounds__(256) void attn_tc(
    const float* __restrict__ Q,
    const float* __restrict__ Kn,
    const float* __restrict__ Vn,
    const float* __restrict__ kc,
    const float* __restrict__ vc,
    float* __restrict__ O)
{
    extern __shared__ float sm[];
    uint32_t smb = smem_u32(sm);
    float* Ps   = sm + AT_PS;
    float* lrow = sm + AT_LROW;
    uint32_t psb = smb + AT_PS * 4;

    int qt = blockIdx.x, h = blockIdx.y, b = blockIdx.z;
    int tid = threadIdx.x, lane = tid & 31, w = tid >> 5;
    int wm = w >> 1, wn = w & 1;
    int g = lane >> 2, tg = lane & 3;
    int q0 = qt * 64;
    size_t bh = (size_t)b * NH + h;

    if (tid < 64) lrow[tid] = 0.f;

    // ldmatrix lane offsets
    int lr16 = lane & 15;
    int lc4  = ((lane >> 4) & 1) * 4;
    int br   = (lane & 7) + ((lane >> 4) & 1) * 8;
    int bc4  = ((lane >> 3) & 1) * 4;
    uint32_t k_off[2];
#pragma unroll
    for (int njp = 0; njp < 2; ++njp)
        k_off[njp] = (uint32_t)(((wn * 32 + njp * 16 + br) * DPADK + bc4) * 4);
    uint32_t p_off = (uint32_t)(((wm * 16 + lr16) * PPAD + lc4) * 4);

    const float* kcb = kc + bh * CACHEDLEN * HD;
    const float* vcb = vc + bh * CACHEDLEN * HD;
    const float* knb = Kn + bh * SEQ * HD;
    const float* vnb = Vn + bh * SEQ * HD;

    // Q fragments in registers (already scaled+rounded in gmem)
    const float* Qg = Q + (bh * SEQ + q0) * HD;
    int r0 = wm * 16 + g;
    uint32_t qf[16][4];
#pragma unroll
    for (int s = 0; s < 16; ++s) {
        int k0 = 8 * s + tg;
        qf[s][0] = __float_as_uint(Qg[(size_t)r0 * HD + k0]);
        qf[s][1] = __float_as_uint(Qg[(size_t)(r0 + 8) * HD + k0]);
        qf[s][2] = __float_as_uint(Qg[(size_t)r0 * HD + k0 + 4]);
        qf[s][3] = __float_as_uint(Qg[(size_t)(r0 + 8) * HD + k0 + 4]);
    }

    float oa[8][4];
#pragma unroll
    for (int j = 0; j < 8; ++j)
#pragma unroll
        for (int r = 0; r < 4; ++r) oa[j][r] = 0.f;

    int nt = (CACHEDLEN + q0 + 64) / 64;
    load_kv(kcb, vcb, knb, vnb, 0, smb, tid);
    CP_COMMIT();

    for (int it = 0; it < nt; ++it) {
        if (it + 1 < nt)
            load_kv(kcb, vcb, knb, vnb, (it + 1) * 64,
                    smb + (uint32_t)(((it + 1) & 1) * KV_STAGE * 4), tid);
        CP_COMMIT();
        CP_WAIT1();
        __syncthreads();

        uint32_t sK = smb + (uint32_t)((it & 1) * KV_STAGE * 4);
        const float* Vs = sm + (it & 1) * KV_STAGE + 64 * DPADK;

        // ---- S = Q K^T : warp tile 16x32, K frags via ldmatrix ----
        float sc[4][4];
#pragma unroll
        for (int nj = 0; nj < 4; ++nj)
#pragma unroll
            for (int r = 0; r < 4; ++r) sc[nj][r] = 0.f;

#pragma unroll
        for (int s = 0; s < 16; ++s) {
            uint32_t koff = (uint32_t)(s * 32);
            uint32_t kq[2][4];
            ldsm_x4(kq[0], sK + k_off[0] + koff);
            ldsm_x4(kq[1], sK + k_off[1] + koff);
            mma_tf32(sc[0], qf[s], &kq[0][0]);
            mma_tf32(sc[1], qf[s], &kq[0][2]);
            mma_tf32(sc[2], qf[s], &kq[1][0]);
            mma_tf32(sc[3], qf[s], &kq[1][2]);
        }

        // ---- exp + mask + row sums + store P (tf32-rounded) ----
        int qa0 = CACHEDLEN + q0 + wm * 16 + g;
        int tb  = it * 64 + wn * 32;
        float rs0 = 0.f, rs1 = 0.f;
#pragma unroll
        for (int nj = 0; nj < 4; ++nj) {
            int c0 = tb + nj * 8 + 2 * tg;
            float p00 = (c0     <= qa0    ) ? roundtf(__expf(sc[nj][0])) : 0.f;
            float p01 = (c0 + 1 <= qa0    ) ? roundtf(__expf(sc[nj][1])) : 0.f;
            float p10 = (c0     <= qa0 + 8) ? roundtf(__expf(sc[nj][2])) : 0.f;
            float p11 = (c0 + 1 <= qa0 + 8) ? roundtf(__expf(sc[nj][3])) : 0.f;
            rs0 += p00 + p01;
            rs1 += p10 + p11;
            int pr = wm * 16 + g;
            int pcol = wn * 32 + nj * 8 + 2 * tg;
            *reinterpret_cast<float2*>(&Ps[pr * PPAD + pcol])       = make_float2(p00, p01);
            *reinterpret_cast<float2*>(&Ps[(pr + 8) * PPAD + pcol]) = make_float2(p10, p11);
        }
        rs0 += __shfl_xor_sync(0xffffffffu, rs0, 1);
        rs0 += __shfl_xor_sync(0xffffffffu, rs0, 2);
        rs1 += __shfl_xor_sync(0xffffffffu, rs1, 1);
        rs1 += __shfl_xor_sync(0xffffffffu, rs1, 2);
        if (tg == 0) {
            atomicAdd(&lrow[wm * 16 + g], rs0);
            atomicAdd(&lrow[wm * 16 + g + 8], rs1);
        }
        __syncthreads();

        // ---- O += P V : P frags via ldmatrix, V scalar (conflict-free pad) ----
#pragma unroll
        for (int s = 0; s < 8; ++s) {
            uint32_t pq[4];
            ldsm_x4(pq, psb + p_off + (uint32_t)(s * 32));
            const float* vrow0 = Vs + (8 * s + tg) * VPADV;
            const float* vrow1 = vrow0 + 4 * VPADV;
#pragma unroll
            for (int nj = 0; nj < 8; ++nj) {
                int d0 = wn * 64 + nj * 8 + g;
                uint32_t bf[2];
                bf[0] = __float_as_uint(vrow0[d0]);
                bf[1] = __float_as_uint(vrow1[d0]);
                mma_tf32(oa[nj], pq, bf);
            }
        }
        __syncthreads();
    }

    float inv0 = 1.f / lrow[wm * 16 + g];
    float inv1 = 1.f / lrow[wm * 16 + g + 8];
    int row0 = q0 + wm * 16 + g;
#pragma unroll
    for (int nj = 0; nj < 8; ++nj) {
        int d = wn * 64 + nj * 8 + 2 * tg;
        float* dst0 = O + ((size_t)b * SEQ + row0) * DMODEL + h * HD + d;
        float* dst1 = O + ((size_t)b * SEQ + row0 + 8) * DMODEL + h * HD + d;
        *reinterpret_cast<float2*>(dst0) =
            make_float2(roundtf(oa[nj][0] * inv0), roundtf(oa[nj][1] * inv0));
        *reinterpret_cast<float2*>(dst1) =
            make_float2(roundtf(oa[nj][2] * inv1), roundtf(oa[nj][3] * inv1));
    }
}

// ---------------- launch ----------------
extern "C" void kernel_launch(void* const* d_in, const int* in_sizes, int n_in,
                              void* d_out, int out_size)
{
    const float* X  = (const float*)d_in[0];
    const float* Wq = (const float*)d_in[1];
    const float* Wk = (const float*)d_in[2];
    const float* Wv = (const float*)d_in[3];
    const float* Wo = (const float*)d_in[4];
    const float* kc = (const float*)d_in[5];
    const float* vc = (const float*)d_in[6];

    float *Qp, *Kp, *Vp, *Ap, *Xp, *Wp, *Kcp, *Vcp;
    cudaGetSymbolAddress((void**)&Qp,  g_Q);
    cudaGetSymbolAddress((void**)&Kp,  g_Kn);
    cudaGetSymbolAddress((void**)&Vp,  g_Vn);
    cudaGetSymbolAddress((void**)&Ap,  g_At);
    cudaGetSymbolAddress((void**)&Xp,  g_X);
    cudaGetSymbolAddress((void**)&Wp,  g_Wr);
    cudaGetSymbolAddress((void**)&Kcp, g_Kc);
    cudaGetSymbolAddress((void**)&Vcp, g_Vc);

    cudaFuncSetAttribute(gemm_mma<0>, cudaFuncAttributeMaxDynamicSharedMemorySize, GEMM_SMEM);
    cudaFuncSetAttribute(gemm_mma<1>, cudaFuncAttributeMaxDynamicSharedMemorySize, GEMM_SMEM);
    cudaFuncSetAttribute(gemm_mma<2>, cudaFuncAttributeMaxDynamicSharedMemorySize, GEMM_SMEM);
    cudaFuncSetAttribute(attn_tc, cudaFuncAttributeMaxDynamicSharedMemorySize, ATTN_SMEM);

    const int NX = BATCH * SEQ * DMODEL / 4;      // float4 counts
    const int NW = DMODEL * DMODEL / 4;
    const int NC = BATCH * NH * CACHEDLEN * HD / 4;

    round_tf32_k<<<NX / 1024, 256>>>((const float4*)X,  (float4*)Xp,  NX);
    round_tf32_k<<<NW / 1024, 256>>>((const float4*)Wq, (float4*)(Wp + 0L * DMODEL * DMODEL), NW);
    round_tf32_k<<<NW / 1024, 256>>>((const float4*)Wk, (float4*)(Wp + 1L * DMODEL * DMODEL), NW);
    round_tf32_k<<<NW / 1024, 256>>>((const float4*)Wv, (float4*)(Wp + 2L * DMODEL * DMODEL), NW);
    round_tf32_k<<<NW / 1024, 256>>>((const float4*)Wo, (float4*)(Wp + 3L * DMODEL * DMODEL), NW);
    round_tf32_k<<<NC / 1024, 256>>>((const float4*)kc, (float4*)Kcp, NC);
    round_tf32_k<<<NC / 1024, 256>>>((const float4*)vc, (float4*)Vcp, NC);

    dim3 gg(DMODEL / 128, (BATCH * SEQ) / 128);

    gemm_mma<2><<<gg, 256, GEMM_SMEM>>>(Xp, Wp + 0L * DMODEL * DMODEL, Qp);
    gemm_mma<1><<<gg, 256, GEMM_SMEM>>>(Xp, Wp + 1L * DMODEL * DMODEL, Kp);
    gemm_mma<1><<<gg, 256, GEMM_SMEM>>>(Xp, Wp + 2L * DMODEL * DMODEL, Vp);

    attn_tc<<<dim3(SEQ / 64, NH, BATCH), 256, ATTN_SMEM>>>(Qp, Kp, Vp, Kcp, Vcp, Ap);

    gemm_mma<0><<<gg, 256, GEMM_SMEM>>>(Ap, Wp + 3L * DMODEL * DMODEL, (float*)d_out);
}

// round 7
// speedup vs baseline: 1.2710x; 1.0937x over previous
#include <cuda_runtime.h>
#include <cstdint>
#include <math.h>

#define BATCH 2
#define SEQ   2048
#define DMODEL 2048
#define NH    16
#define HD    128
#define CACHEDLEN 2048

// ---------------- scratch (static device globals) ----------------
__device__ float g_Q [(size_t)BATCH*NH*SEQ*HD];   // [B,H,S,HD] pre-scaled+rounded
__device__ float g_Kn[(size_t)BATCH*NH*SEQ*HD];   // [B,H,S,HD] rounded
__device__ float g_Vn[(size_t)BATCH*NH*SEQ*HD];   // [B,H,S,HD] rounded
__device__ float g_At[(size_t)BATCH*SEQ*DMODEL];  // [B,S,D]    rounded
__device__ float g_X [(size_t)BATCH*SEQ*DMODEL];  // rounded hidden states
__device__ float g_Wr[(size_t)4*DMODEL*DMODEL];   // rounded Wq,Wk,Wv,Wo
__device__ float g_Kc[(size_t)BATCH*NH*CACHEDLEN*HD];  // rounded k_cache
__device__ float g_Vc[(size_t)BATCH*NH*CACHEDLEN*HD];  // rounded v_cache

// ================= helpers =================
__device__ __forceinline__ uint32_t smem_u32(const void* p) {
    uint32_t a;
    asm("{ .reg .u64 t; cvta.to.shared.u64 t, %1; cvt.u32.u64 %0, t; }" : "=r"(a) : "l"(p));
    return a;
}
__device__ __forceinline__ void cp_async16(uint32_t saddr, const void* gptr) {
    asm volatile("cp.async.cg.shared.global [%0], [%1], 16;\n" :: "r"(saddr), "l"(gptr));
}
#define CP_COMMIT() asm volatile("cp.async.commit_group;\n" ::: "memory")
#define CP_WAIT1()  asm volatile("cp.async.wait_group 1;\n" ::: "memory")

__device__ __forceinline__ uint32_t f2tf32(float f) {
    uint32_t r;
    asm("cvt.rna.tf32.f32 %0, %1;" : "=r"(r) : "f"(f));
    return r;
}
__device__ __forceinline__ float roundtf(float f) { return __uint_as_float(f2tf32(f)); }

__device__ __forceinline__ void mma_tf32(float c[4], const uint32_t a[4], const uint32_t b[2]) {
    asm volatile(
        "mma.sync.aligned.m16n8k8.row.col.f32.tf32.tf32.f32 "
        "{%0,%1,%2,%3}, {%4,%5,%6,%7}, {%8,%9}, {%0,%1,%2,%3};"
        : "+f"(c[0]), "+f"(c[1]), "+f"(c[2]), "+f"(c[3])
        : "r"(a[0]), "r"(a[1]), "r"(a[2]), "r"(a[3]), "r"(b[0]), "r"(b[1]));
}
__device__ __forceinline__ void ldsm_x4(uint32_t r[4], uint32_t saddr) {
    asm volatile("ldmatrix.sync.aligned.m8n8.x4.shared.b16 {%0,%1,%2,%3}, [%4];"
                 : "=r"(r[0]), "=r"(r[1]), "=r"(r[2]), "=r"(r[3]) : "r"(saddr));
}

// ================= tf32 pre-rounding kernel (4-wide) =================
__global__ __launch_bounds__(256) void round_tf32_k(const float4* __restrict__ in,
                                                    float4* __restrict__ out, int n4)
{
    int i = (blockIdx.x * blockDim.x + threadIdx.x) * 4;
    if (i + 3 < n4) {
        float4 a = in[i], b = in[i+1], c = in[i+2], d = in[i+3];
        a.x=roundtf(a.x); a.y=roundtf(a.y); a.z=roundtf(a.z); a.w=roundtf(a.w);
        b.x=roundtf(b.x); b.y=roundtf(b.y); b.z=roundtf(b.z); b.w=roundtf(b.w);
        c.x=roundtf(c.x); c.y=roundtf(c.y); c.z=roundtf(c.z); c.w=roundtf(c.w);
        d.x=roundtf(d.x); d.y=roundtf(d.y); d.z=roundtf(d.z); d.w=roundtf(d.w);
        out[i] = a; out[i+1] = b; out[i+2] = c; out[i+3] = d;
    }
}

// ================= tf32 mma.sync GEMM =================
#define BK       32
#define NCHUNK   (DMODEL / BK)
#define ROWPAD   36
#define TILE_FLOATS (128 * ROWPAD)
#define STAGE_FLOATS (2 * TILE_FLOATS)
#define NSTAGES  3
#define GEMM_SMEM (NSTAGES * STAGE_FLOATS * 4)

__device__ __forceinline__ void load_stage(const float* __restrict__ A,
                                           const float* __restrict__ W,
                                           int m0, int n0, int k0,
                                           uint32_t sa, int tid)
{
#pragma unroll
    for (int i = 0; i < 4; ++i) {
        int c = tid + 256 * i;
        int row = c >> 3;
        int j = c & 7;
        cp_async16(sa + (uint32_t)(row * (ROWPAD * 4) + j * 16),
                   A + (size_t)(m0 + row) * DMODEL + k0 + j * 4);
    }
    uint32_t sb = sa + TILE_FLOATS * 4;
#pragma unroll
    for (int i = 0; i < 4; ++i) {
        int c = tid + 256 * i;
        int row = c >> 3;
        int j = c & 7;
        cp_async16(sb + (uint32_t)(row * (ROWPAD * 4) + j * 16),
                   W + (size_t)(n0 + row) * DMODEL + k0 + j * 4);
    }
}

// Shared mainloop body: computes acc for tile (m0,n0) with weights W.
__device__ __forceinline__ void gemm_body(const float* __restrict__ A,
                                          const float* __restrict__ W,
                                          uint32_t smb, int tid, int m0, int n0,
                                          float acc[4][4][4])
{
    int lane = tid & 31;
    int w = tid >> 5;
    int wm = w >> 2;
    int wn = w & 3;
    int lr16 = lane & 15;
    int lc4  = ((lane >> 4) & 1) * 4;
    int br   = (lane & 7) + ((lane >> 4) & 1) * 8;
    int bc4  = ((lane >> 3) & 1) * 4;
    uint32_t a_off[4], b_off[2];
#pragma unroll
    for (int mi = 0; mi < 4; ++mi)
        a_off[mi] = (uint32_t)(((wm * 64 + mi * 16 + lr16) * ROWPAD + lc4) * 4);
#pragma unroll
    for (int njp = 0; njp < 2; ++njp)
        b_off[njp] = (uint32_t)(((wn * 32 + njp * 16 + br) * ROWPAD + bc4) * 4);

    load_stage(A, W, m0, n0, 0, smb, tid);
    CP_COMMIT();
    load_stage(A, W, m0, n0, BK, smb + STAGE_FLOATS * 4, tid);
    CP_COMMIT();

    for (int it = 0; it < NCHUNK; ++it) {
        uint32_t sA = smb + (uint32_t)((it % NSTAGES) * STAGE_FLOATS * 4);
        uint32_t sB = sA + TILE_FLOATS * 4;
        CP_WAIT1();
        __syncthreads();

#pragma unroll
        for (int s = 0; s < 4; ++s) {
            uint32_t koff = (uint32_t)(s * 32);
            uint32_t af[4][4], bq[2][4];
#pragma unroll
            for (int mi = 0; mi < 4; ++mi) ldsm_x4(af[mi], sA + a_off[mi] + koff);
#pragma unroll
            for (int njp = 0; njp < 2; ++njp) ldsm_x4(bq[njp], sB + b_off[njp] + koff);
#pragma unroll
            for (int mi = 0; mi < 4; ++mi)
#pragma unroll
                for (int nj = 0; nj < 4; ++nj)
                    mma_tf32(acc[mi][nj], af[mi], &bq[nj >> 1][(nj & 1) * 2]);
        }

        if (it + 2 < NCHUNK)
            load_stage(A, W, m0, n0, (it + 2) * BK,
                       smb + (uint32_t)(((it + 2) % NSTAGES) * STAGE_FLOATS * 4), tid);
        CP_COMMIT();
    }
}

// Fused QKV projection: blockIdx.z selects proj (0=Q scaled, 1=K, 2=V).
__global__ __launch_bounds__(256) void gemm_qkv(const float* __restrict__ A,
                                                const float* __restrict__ W0,
                                                float* __restrict__ Qo,
                                                float* __restrict__ Ko,
                                                float* __restrict__ Vo)
{
    extern __shared__ float sm[];
    uint32_t smb = smem_u32(sm);
    int tid = threadIdx.x;
    int pz = blockIdx.z;
    const float* W = W0 + (size_t)pz * DMODEL * DMODEL;
    float* C = (pz == 0) ? Qo : ((pz == 1) ? Ko : Vo);
    float sc = (pz == 0) ? 0.088388347648318447f : 1.0f;
    int m0 = blockIdx.y * 128, n0 = blockIdx.x * 128;

    float acc[4][4][4];
#pragma unroll
    for (int i = 0; i < 4; ++i)
#pragma unroll
        for (int j = 0; j < 4; ++j)
#pragma unroll
            for (int r = 0; r < 4; ++r) acc[i][j][r] = 0.f;

    gemm_body(A, W, smb, tid, m0, n0, acc);

    int lane = tid & 31;
    int w = tid >> 5, wm = w >> 2, wn = w & 3;
    int g = lane >> 2, tg = lane & 3;
#pragma unroll
    for (int mi = 0; mi < 4; ++mi) {
#pragma unroll
        for (int nj = 0; nj < 4; ++nj) {
            int m = m0 + wm * 64 + mi * 16 + g;
            int n = n0 + wn * 32 + nj * 8 + 2 * tg;
            float v0 = roundtf(acc[mi][nj][0] * sc);
            float v1 = roundtf(acc[mi][nj][1] * sc);
            float v2 = roundtf(acc[mi][nj][2] * sc);
            float v3 = roundtf(acc[mi][nj][3] * sc);
            int h_  = n >> 7;
            int hd_ = n & 127;
            {
                int b_ = m >> 11, s_ = m & 2047;
                *reinterpret_cast<float2*>(
                    C + ((((size_t)b_ * NH + h_) * SEQ + s_) * HD + hd_)) = make_float2(v0, v1);
            }
            {
                int m2 = m + 8;
                int b_ = m2 >> 11, s_ = m2 & 2047;
                *reinterpret_cast<float2*>(
                    C + ((((size_t)b_ * NH + h_) * SEQ + s_) * HD + hd_)) = make_float2(v2, v3);
            }
        }
    }
}

// Output projection: plain row-major out.
__global__ __launch_bounds__(256) void gemm_out(const float* __restrict__ A,
                                                const float* __restrict__ W,
                                                float* __restrict__ C)
{
    extern __shared__ float sm[];
    uint32_t smb = smem_u32(sm);
    int tid = threadIdx.x;
    int m0 = blockIdx.y * 128, n0 = blockIdx.x * 128;

    float acc[4][4][4];
#pragma unroll
    for (int i = 0; i < 4; ++i)
#pragma unroll
        for (int j = 0; j < 4; ++j)
#pragma unroll
            for (int r = 0; r < 4; ++r) acc[i][j][r] = 0.f;

    gemm_body(A, W, smb, tid, m0, n0, acc);

    int lane = tid & 31;
    int w = tid >> 5, wm = w >> 2, wn = w & 3;
    int g = lane >> 2, tg = lane & 3;
#pragma unroll
    for (int mi = 0; mi < 4; ++mi) {
#pragma unroll
        for (int nj = 0; nj < 4; ++nj) {
            int m = m0 + wm * 64 + mi * 16 + g;
            int n = n0 + wn * 32 + nj * 8 + 2 * tg;
            *reinterpret_cast<float2*>(C + (size_t)m * DMODEL + n) =
                make_float2(acc[mi][nj][0], acc[mi][nj][1]);
            *reinterpret_cast<float2*>(C + (size_t)(m + 8) * DMODEL + n) =
                make_float2(acc[mi][nj][2], acc[mi][nj][3]);
        }
    }
}

// ================= tensor-core flash attention, 2 CTAs/SM =================
// KV tile 32, double-buffered. Q tile 64x128 in smem (ldmatrix). 8 warps:
// wm = w>>1 in 0..3 (16 q rows each), wn = w&1 (KV/d split).
#define KVT   32
#define DPADK 132
#define VPADV 136
#define QPAD  132
#define PPAD  36
#define AT_K    0
#define AT_V    (2 * KVT * DPADK)            // 8448
#define AT_QS   (AT_V + 2 * KVT * VPADV)     // 17152
#define AT_PS   (AT_QS + 64 * QPAD)          // 25600
#define AT_LROW (AT_PS + 64 * PPAD)          // 27904
#define ATTN_SMEM ((AT_LROW + 64) * 4)       // 111872 B

__device__ __forceinline__ void load_kv32(const float* __restrict__ kcb,
                                          const float* __restrict__ vcb,
                                          const float* __restrict__ knb,
                                          const float* __restrict__ vnb,
                                          int t0, int st, uint32_t smb, int tid)
{
    uint32_t sk = smb + (uint32_t)((AT_K + st * KVT * DPADK) * 4);
    uint32_t sv = smb + (uint32_t)((AT_V + st * KVT * VPADV) * 4);
#pragma unroll
    for (int i = 0; i < 4; ++i) {
        int idx = tid + 256 * i;          // 0..1023
        int row = idx >> 5;               // 0..31
        int j = idx & 31;
        int t = t0 + row;
        const float *ks, *vs;
        if (t < CACHEDLEN) { ks = kcb + (size_t)t * HD; vs = vcb + (size_t)t * HD; }
        else               { ks = knb + (size_t)(t - CACHEDLEN) * HD;
                             vs = vnb + (size_t)(t - CACHEDLEN) * HD; }
        cp_async16(sk + (uint32_t)(row * (DPADK * 4) + j * 16), ks + j * 4);
        cp_async16(sv + (uint32_t)(row * (VPADV * 4) + j * 16), vs + j * 4);
    }
}

__global__ __launch_bounds__(256, 2) void attn_tc(
    const float* __restrict__ Q,
    const float* __restrict__ Kn,
    const float* __restrict__ Vn,
    const float* __restrict__ kc,
    const float* __restrict__ vc,
    float* __restrict__ O)
{
    extern __shared__ float sm[];
    uint32_t smb = smem_u32(sm);
    float* Ps   = sm + AT_PS;
    float* lrow = sm + AT_LROW;
    uint32_t qsb = smb + AT_QS * 4;
    uint32_t psb = smb + AT_PS * 4;

    int qt = blockIdx.x, h = blockIdx.y, b = blockIdx.z;
    int tid = threadIdx.x, lane = tid & 31, w = tid >> 5;
    int wm = w >> 1, wn = w & 1;
    int g = lane >> 2, tg = lane & 3;
    int q0 = qt * 64;
    size_t bh = (size_t)b * NH + h;

    if (tid < 64) lrow[tid] = 0.f;

    // ldmatrix lane offsets
    int lr16 = lane & 15;
    int lc4  = ((lane >> 4) & 1) * 4;
    int br   = (lane & 7) + ((lane >> 4) & 1) * 8;
    int bc4  = ((lane >> 3) & 1) * 4;
    uint32_t a_off = (uint32_t)(((wm * 16 + lr16) * QPAD + lc4) * 4);
    uint32_t k_off = (uint32_t)(((wn * 16 + br) * DPADK + bc4) * 4);
    uint32_t p_off = (uint32_t)(((wm * 16 + lr16) * PPAD + lc4) * 4);

    const float* kcb = kc + bh * CACHEDLEN * HD;
    const float* vcb = vc + bh * CACHEDLEN * HD;
    const float* knb = Kn + bh * SEQ * HD;
    const float* vnb = Vn + bh * SEQ * HD;

    // Q tile -> smem (cp.async), part of group 0
    const float* Qg = Q + (bh * SEQ + q0) * HD;
#pragma unroll
    for (int i = 0; i < 8; ++i) {
        int idx = tid + 256 * i;          // 0..2047
        int row = idx >> 5;               // 0..63
        int j = idx & 31;
        cp_async16(qsb + (uint32_t)(row * (QPAD * 4) + j * 16),
                   Qg + (size_t)row * HD + j * 4);
    }

    float oa[8][4];
#pragma unroll
    for (int j = 0; j < 8; ++j)
#pragma unroll
        for (int r = 0; r < 4; ++r) oa[j][r] = 0.f;

    int nt = (CACHEDLEN + q0 + 64) / KVT;
    load_kv32(kcb, vcb, knb, vnb, 0, 0, smb, tid);
    CP_COMMIT();                          // group: Q + KV0

    for (int it = 0; it < nt; ++it) {
        if (it + 1 < nt)
            load_kv32(kcb, vcb, knb, vnb, (it + 1) * KVT, (it + 1) & 1, smb, tid);
        CP_COMMIT();
        CP_WAIT1();
        __syncthreads();

        uint32_t sK = smb + (uint32_t)((AT_K + (it & 1) * KVT * DPADK) * 4);
        const float* Vs = sm + AT_V + (it & 1) * KVT * VPADV;

        // ---- S = Q K^T : warp tile 16x16 ----
        float sc[2][4];
#pragma unroll
        for (int nj = 0; nj < 2; ++nj)
#pragma unroll
            for (int r = 0; r < 4; ++r) sc[nj][r] = 0.f;

#pragma unroll
        for (int s = 0; s < 16; ++s) {
            uint32_t koff = (uint32_t)(s * 32);
            uint32_t af[4], kq[4];
            ldsm_x4(af, qsb + a_off + koff);
            ldsm_x4(kq, sK + k_off + koff);
            mma_tf32(sc[0], af, &kq[0]);
            mma_tf32(sc[1], af, &kq[2]);
        }

        // ---- exp + mask + row sums + store P (tf32-rounded) ----
        int qa0 = CACHEDLEN + q0 + wm * 16 + g;
        int tb  = it * KVT + wn * 16;
        float rs0 = 0.f, rs1 = 0.f;
#pragma unroll
        for (int nj = 0; nj < 2; ++nj) {
            int c0 = tb + nj * 8 + 2 * tg;
            float p00 = (c0     <= qa0    ) ? roundtf(__expf(sc[nj][0])) : 0.f;
            float p01 = (c0 + 1 <= qa0    ) ? roundtf(__expf(sc[nj][1])) : 0.f;
            float p10 = (c0     <= qa0 + 8) ? roundtf(__expf(sc[nj][2])) : 0.f;
            float p11 = (c0 + 1 <= qa0 + 8) ? roundtf(__expf(sc[nj][3])) : 0.f;
            rs0 += p00 + p01;
            rs1 += p10 + p11;
            int pr = wm * 16 + g;
            int pcol = wn * 16 + nj * 8 + 2 * tg;
            *reinterpret_cast<float2*>(&Ps[pr * PPAD + pcol])       = make_float2(p00, p01);
            *reinterpret_cast<float2*>(&Ps[(pr + 8) * PPAD + pcol]) = make_float2(p10, p11);
        }
        rs0 += __shfl_xor_sync(0xffffffffu, rs0, 1);
        rs0 += __shfl_xor_sync(0xffffffffu, rs0, 2);
        rs1 += __shfl_xor_sync(0xffffffffu, rs1, 1);
        rs1 += __shfl_xor_sync(0xffffffffu, rs1, 2);
        if (tg == 0) {
            atomicAdd(&lrow[wm * 16 + g], rs0);
            atomicAdd(&lrow[wm * 16 + g + 8], rs1);
        }
        __syncthreads();

        // ---- O += P V : P frags via ldmatrix, V scalar (conflict-free) ----
#pragma unroll
        for (int s = 0; s < 4; ++s) {
            uint32_t pq[4];
            ldsm_x4(pq, psb + p_off + (uint32_t)(s * 32));
            const float* vrow0 = Vs + (8 * s + tg) * VPADV;
            const float* vrow1 = vrow0 + 4 * VPADV;
#pragma unroll
            for (int nj = 0; nj < 8; ++nj) {
                int d0 = wn * 64 + nj * 8 + g;
                uint32_t bf[2];
                bf[0] = __float_as_uint(vrow0[d0]);
                bf[1] = __float_as_uint(vrow1[d0]);
                mma_tf32(oa[nj], pq, bf);
            }
        }
        __syncthreads();
    }

    float inv0 = 1.f / lrow[wm * 16 + g];
    float inv1 = 1.f / lrow[wm * 16 + g + 8];
    int row0 = q0 + wm * 16 + g;
#pragma unroll
    for (int nj = 0; nj < 8; ++nj) {
        int d = wn * 64 + nj * 8 + 2 * tg;
        float* dst0 = O + ((size_t)b * SEQ + row0) * DMODEL + h * HD + d;
        float* dst1 = O + ((size_t)b * SEQ + row0 + 8) * DMODEL + h * HD + d;
        *reinterpret_cast<float2*>(dst0) =
            make_float2(roundtf(oa[nj][0] * inv0), roundtf(oa[nj][1] * inv0));
        *reinterpret_cast<float2*>(dst1) =
            make_float2(roundtf(oa[nj][2] * inv1), roundtf(oa[nj][3] * inv1));
    }
}

// ---------------- launch ----------------
extern "C" void kernel_launch(void* const* d_in, const int* in_sizes, int n_in,
                              void* d_out, int out_size)
{
    const float* X  = (const float*)d_in[0];
    const float* Wq = (const float*)d_in[1];
    const float* Wk = (const float*)d_in[2];
    const float* Wv = (const float*)d_in[3];
    const float* Wo = (const float*)d_in[4];
    const float* kc = (const float*)d_in[5];
    const float* vc = (const float*)d_in[6];

    float *Qp, *Kp, *Vp, *Ap, *Xp, *Wp, *Kcp, *Vcp;
    cudaGetSymbolAddress((void**)&Qp,  g_Q);
    cudaGetSymbolAddress((void**)&Kp,  g_Kn);
    cudaGetSymbolAddress((void**)&Vp,  g_Vn);
    cudaGetSymbolAddress((void**)&Ap,  g_At);
    cudaGetSymbolAddress((void**)&Xp,  g_X);
    cudaGetSymbolAddress((void**)&Wp,  g_Wr);
    cudaGetSymbolAddress((void**)&Kcp, g_Kc);
    cudaGetSymbolAddress((void**)&Vcp, g_Vc);

    cudaFuncSetAttribute(gemm_qkv, cudaFuncAttributeMaxDynamicSharedMemorySize, GEMM_SMEM);
    cudaFuncSetAttribute(gemm_out, cudaFuncAttributeMaxDynamicSharedMemorySize, GEMM_SMEM);
    cudaFuncSetAttribute(attn_tc,  cudaFuncAttributeMaxDynamicSharedMemorySize, ATTN_SMEM);

    const int NX = BATCH * SEQ * DMODEL / 4;
    const int NW = DMODEL * DMODEL / 4;
    const int NC = BATCH * NH * CACHEDLEN * HD / 4;

    round_tf32_k<<<NX / 1024, 256>>>((const float4*)X,  (float4*)Xp,  NX);
    round_tf32_k<<<NW / 1024, 256>>>((const float4*)Wq, (float4*)(Wp + 0L * DMODEL * DMODEL), NW);
    round_tf32_k<<<NW / 1024, 256>>>((const float4*)Wk, (float4*)(Wp + 1L * DMODEL * DMODEL), NW);
    round_tf32_k<<<NW / 1024, 256>>>((const float4*)Wv, (float4*)(Wp + 2L * DMODEL * DMODEL), NW);
    round_tf32_k<<<NW / 1024, 256>>>((const float4*)Wo, (float4*)(Wp + 3L * DMODEL * DMODEL), NW);
    round_tf32_k<<<NC / 1024, 256>>>((const float4*)kc, (float4*)Kcp, NC);
    round_tf32_k<<<NC / 1024, 256>>>((const float4*)vc, (float4*)Vcp, NC);

    dim3 gq(DMODEL / 128, (BATCH * SEQ) / 128, 3);   // fused QKV
    gemm_qkv<<<gq, 256, GEMM_SMEM>>>(Xp, Wp, Qp, Kp, Vp);

    attn_tc<<<dim3(SEQ / 64, NH, BATCH), 256, ATTN_SMEM>>>(Qp, Kp, Vp, Kcp, Vcp, Ap);

    dim3 gg(DMODEL / 128, (BATCH * SEQ) / 128);
    gemm_out<<<gg, 256, GEMM_SMEM>>>(Ap, Wp + 3L * DMODEL * DMODEL, (float*)d_out);
}